// round 9
// baseline (speedup 1.0000x reference)
#include <cuda_runtime.h>
#include <math.h>

// TwoLayerNetwork: ConstantCurrentLIFEncoder -> LIFCell -> LILinearCell, T=32,
// then max over timesteps and log_softmax.
//
// Constants: DT*TAU_MEM_INV = 0.1 (decay 0.9), DT*TAU_SYN_INV = 0.2 (decay 0.8),
// V_TH = 1.0.
//
// EXACT per-row fast path (proof): v_enc follows v' = 0.9 v + 0.1 x from 0, so
// v_enc <= max_j x_j for all t. A spike needs v_enc > 1.0, so if ALL pixels of
// a row are <= 1.0 that row never spikes anywhere downstream: v_out stays 0 and
// the answer is log_softmax(zeros) = -log(10). Rows with a pixel > 1.0 run the
// full bit-exact simulator below.
//
// FINAL (R2..R8 sweep conclusion): bench time is 6.6-6.9us for every
// occupancy/regs/load-width/grid/rows-per-warp configuration; DRAM pinned at
// ~2.1TB/s; a trivial second kernel alone costs ~5us. Duration = one-shot
// launch/clock-ramp floor + mandatory 12.8MB scan at the short-kernel DRAM
// ceiling. This is the twice-measured-fastest configuration (6.624us).

#define NT 32
#define NPL 25   // neurons per lane (25*32 = 800 >= 784)

__global__ __launch_bounds__(128) void snn_kernel(
    const float* __restrict__ image,   // [4096, 784]
    const float* __restrict__ W,       // [10, 784]
    float* __restrict__ out)           // [4096, 10]
{
    const int lane = threadIdx.x & 31;
    const int b = blockIdx.x * 4 + (threadIdx.x >> 5);

    // Unconditional early write of the spike-free answer. Hot rows overwrite
    // below in program order (same thread), so the final value is always right.
    if (lane < 10)
        out[(size_t)b * 10 + lane] = -2.302585093f;  // log_softmax(zeros)

    const float* x = image + (size_t)b * 784;
    const float4* x4 = (const float4*)x;   // 196 vec4 per row

    // ---- vectorized row-max scan ----
    float m = 0.0f;
#pragma unroll
    for (int i = 0; i < 6; i++) {
        const float4 v = __ldg(&x4[lane + 32 * i]);
        m = fmaxf(m, fmaxf(fmaxf(v.x, v.y), fmaxf(v.z, v.w)));
    }
    if (lane < 4) {   // 196 = 6*32 + 4
        const float4 v = __ldg(&x4[lane + 192]);
        m = fmaxf(m, fmaxf(fmaxf(v.x, v.y), fmaxf(v.z, v.w)));
    }

    // Row provably spike-free -> constant already written, done.
    if (!__any_sync(0xffffffffu, m > 1.0f))
        return;

    // ---- Full general simulation (bit-exact verified R1 path) ----
    // Only rows that can actually spike reach here; reload in sim layout
    // (L2-hot). Register/spill cost is paid only on this path.
    float xs[NPL];   // 0.1 * x
    float ve[NPL];   // encoder membrane
    float v0[NPL];   // hidden membrane
    float i0[NPL];   // hidden synaptic current
#pragma unroll
    for (int i = 0; i < NPL; i++) {
        const int j = lane + 32 * i;
        xs[i] = (j < 784) ? 0.1f * __ldg(&x[j]) : 0.0f;
        ve[i] = 0.0f; v0[i] = 0.0f; i0[i] = 0.0f;
    }

    float v_out = 0.0f, i_out = 0.0f, vmax = -INFINITY;

#pragma unroll 1
    for (int t = 0; t < NT; t++) {
        unsigned tmask = 0u;
#pragma unroll
        for (int i = 0; i < NPL; i++) {
            // encoder LIF step
            float v = fmaf(ve[i], 0.9f, xs[i]);
            const bool pe = (v > 1.0f);
            const float zef = pe ? 1.0f : 0.0f;
            ve[i] = pe ? 0.0f : v;
            // hidden LIF step (reads old v0, i0)
            const float vd = fmaf(v0[i], 0.9f, 0.1f * i0[i]);
            const bool p0 = (vd > 1.0f);
            v0[i] = p0 ? 0.0f : vd;
            i0[i] = fmaf(i0[i], 0.8f, zef);
            if (p0) tmask |= (1u << i);
        }

        // s[k] = sum_j z0[j] * W[k, j]; zero on spike-free steps.
        float s = 0.0f;
        if (__any_sync(0xffffffffu, tmask != 0u)) {
            float acc[10];
#pragma unroll
            for (int k = 0; k < 10; k++) acc[k] = 0.0f;
            unsigned mm = tmask;
            while (mm) {
                const int i = __ffs(mm) - 1;
                mm &= (mm - 1u);
                const int j = lane + 32 * i;
#pragma unroll
                for (int k = 0; k < 10; k++)
                    acc[k] += __ldg(&W[k * 784 + j]);
            }
#pragma unroll
            for (int k = 0; k < 10; k++) {
#pragma unroll
                for (int off = 16; off; off >>= 1)
                    acc[k] += __shfl_xor_sync(0xffffffffu, acc[k], off);
            }
            s = acc[0];
#pragma unroll
            for (int k = 1; k < 10; k++) s = (lane == k) ? acc[k] : s;
        }

        const float i_jump = i_out + s;
        v_out = fmaf(v_out, 0.9f, 0.1f * i_jump);
        i_out = 0.8f * i_jump;
        vmax = fmaxf(vmax, v_out);
    }

    // log_softmax over the 10 classes held by lanes 0..9
    const float v = (lane < 10) ? vmax : -INFINITY;
    float mred = v;
#pragma unroll
    for (int off = 16; off; off >>= 1)
        mred = fmaxf(mred, __shfl_xor_sync(0xffffffffu, mred, off));
    float e = (lane < 10) ? expf(v - mred) : 0.0f;
    float se = e;
#pragma unroll
    for (int off = 16; off; off >>= 1)
        se += __shfl_xor_sync(0xffffffffu, se, off);

    if (lane < 10)
        out[(size_t)b * 10 + lane] = v - mred - logf(se);
}

extern "C" void kernel_launch(void* const* d_in, const int* in_sizes, int n_in,
                              void* d_out, int out_size) {
    const float* image = (const float*)d_in[0];  // [4096,1,28,28] fp32
    const float* W     = (const float*)d_in[1];  // [10,784] fp32
    float* out         = (float*)d_out;          // [4096,10] fp32
    (void)in_sizes; (void)n_in; (void)out_size;

    snn_kernel<<<1024, 128>>>(image, W, out);
}

// round 11
// speedup vs baseline: 1.0047x; 1.0047x over previous
#include <cuda_runtime.h>
#include <math.h>

// TwoLayerNetwork: ConstantCurrentLIFEncoder -> LIFCell -> LILinearCell, T=32,
// then max over timesteps and log_softmax.
//
// Constants: DT*TAU_MEM_INV = 0.1 (decay 0.9), DT*TAU_SYN_INV = 0.2 (decay 0.8),
// V_TH = 1.0.
//
// EXACT per-row fast path (proof): v_enc follows v' = 0.9 v + 0.1 x from 0, so
// v_enc <= max_j x_j for all t. A spike needs v_enc > 1.0, so if ALL pixels of
// a row are <= 1.0 that row never spikes anywhere downstream: v_out stays 0 and
// the answer is log_softmax(zeros) = -log(10). Rows with a pixel > 1.0 run the
// full bit-exact simulator below.
//
// R11 = R10 retry: sm_103a ptxas requires .v8.b32/.v4.b64 with .L2::evict_last,
// so the scan uses 256-bit ld.global.nc.L2::evict_last.v4.b64 loads
// (row = 3136B = 98 x 32B chunks: 3 full-warp loads + 2-chunk tail).
// Goal: keep the 12.8MB read-only image L2-resident across graph replays.

#define NT 32
#define NPL 25   // neurons per lane (25*32 = 800 >= 784)

// 32-byte L2-persist load -> max of its 8 floats.
__device__ __forceinline__ float ldg_keep_max8(const char* p) {
    unsigned long long a, b, c, d;
    asm volatile("ld.global.nc.L2::evict_last.v4.b64 {%0,%1,%2,%3}, [%4];"
                 : "=l"(a), "=l"(b), "=l"(c), "=l"(d) : "l"(p));
    float m = __uint_as_float((unsigned)a);
    m = fmaxf(m, __uint_as_float((unsigned)(a >> 32)));
    m = fmaxf(m, __uint_as_float((unsigned)b));
    m = fmaxf(m, __uint_as_float((unsigned)(b >> 32)));
    m = fmaxf(m, __uint_as_float((unsigned)c));
    m = fmaxf(m, __uint_as_float((unsigned)(c >> 32)));
    m = fmaxf(m, __uint_as_float((unsigned)d));
    m = fmaxf(m, __uint_as_float((unsigned)(d >> 32)));
    return m;
}

__global__ __launch_bounds__(128) void snn_kernel(
    const float* __restrict__ image,   // [4096, 784]
    const float* __restrict__ W,       // [10, 784]
    float* __restrict__ out)           // [4096, 10]
{
    const int lane = threadIdx.x & 31;
    const int b = blockIdx.x * 4 + (threadIdx.x >> 5);

    // Unconditional early write of the spike-free answer. Hot rows overwrite
    // below in program order (same thread), so the final value is always right.
    if (lane < 10)
        out[(size_t)b * 10 + lane] = -2.302585093f;  // log_softmax(zeros)

    const float* x = image + (size_t)b * 784;
    const char* xb = (const char*)x;   // row = 3136 bytes = 98 x 32B chunks

    // ---- vectorized row-max scan: 3 full-warp 256-bit loads + 2-chunk tail ----
    float m = 0.0f;
#pragma unroll
    for (int i = 0; i < 3; i++)
        m = fmaxf(m, ldg_keep_max8(xb + ((size_t)(lane + 32 * i) << 5)));
    if (lane < 2)   // chunks 96, 97
        m = fmaxf(m, ldg_keep_max8(xb + ((size_t)(96 + lane) << 5)));

    // Row provably spike-free -> constant already written, done.
    if (!__any_sync(0xffffffffu, m > 1.0f))
        return;

    // ---- Full general simulation (bit-exact verified R1 path) ----
    // Only rows that can actually spike reach here; reload in sim layout
    // (L2-hot). Register/spill cost is paid only on this path.
    float xs[NPL];   // 0.1 * x
    float ve[NPL];   // encoder membrane
    float v0[NPL];   // hidden membrane
    float i0[NPL];   // hidden synaptic current
#pragma unroll
    for (int i = 0; i < NPL; i++) {
        const int j = lane + 32 * i;
        xs[i] = (j < 784) ? 0.1f * __ldg(&x[j]) : 0.0f;
        ve[i] = 0.0f; v0[i] = 0.0f; i0[i] = 0.0f;
    }

    float v_out = 0.0f, i_out = 0.0f, vmax = -INFINITY;

#pragma unroll 1
    for (int t = 0; t < NT; t++) {
        unsigned tmask = 0u;
#pragma unroll
        for (int i = 0; i < NPL; i++) {
            // encoder LIF step
            float v = fmaf(ve[i], 0.9f, xs[i]);
            const bool pe = (v > 1.0f);
            const float zef = pe ? 1.0f : 0.0f;
            ve[i] = pe ? 0.0f : v;
            // hidden LIF step (reads old v0, i0)
            const float vd = fmaf(v0[i], 0.9f, 0.1f * i0[i]);
            const bool p0 = (vd > 1.0f);
            v0[i] = p0 ? 0.0f : vd;
            i0[i] = fmaf(i0[i], 0.8f, zef);
            if (p0) tmask |= (1u << i);
        }

        // s[k] = sum_j z0[j] * W[k, j]; zero on spike-free steps.
        float s = 0.0f;
        if (__any_sync(0xffffffffu, tmask != 0u)) {
            float acc[10];
#pragma unroll
            for (int k = 0; k < 10; k++) acc[k] = 0.0f;
            unsigned mm = tmask;
            while (mm) {
                const int i = __ffs(mm) - 1;
                mm &= (mm - 1u);
                const int j = lane + 32 * i;
#pragma unroll
                for (int k = 0; k < 10; k++)
                    acc[k] += __ldg(&W[k * 784 + j]);
            }
#pragma unroll
            for (int k = 0; k < 10; k++) {
#pragma unroll
                for (int off = 16; off; off >>= 1)
                    acc[k] += __shfl_xor_sync(0xffffffffu, acc[k], off);
            }
            s = acc[0];
#pragma unroll
            for (int k = 1; k < 10; k++) s = (lane == k) ? acc[k] : s;
        }

        const float i_jump = i_out + s;
        v_out = fmaf(v_out, 0.9f, 0.1f * i_jump);
        i_out = 0.8f * i_jump;
        vmax = fmaxf(vmax, v_out);
    }

    // log_softmax over the 10 classes held by lanes 0..9
    const float v = (lane < 10) ? vmax : -INFINITY;
    float mred = v;
#pragma unroll
    for (int off = 16; off; off >>= 1)
        mred = fmaxf(mred, __shfl_xor_sync(0xffffffffu, mred, off));
    float e = (lane < 10) ? expf(v - mred) : 0.0f;
    float se = e;
#pragma unroll
    for (int off = 16; off; off >>= 1)
        se += __shfl_xor_sync(0xffffffffu, se, off);

    if (lane < 10)
        out[(size_t)b * 10 + lane] = v - mred - logf(se);
}

extern "C" void kernel_launch(void* const* d_in, const int* in_sizes, int n_in,
                              void* d_out, int out_size) {
    const float* image = (const float*)d_in[0];  // [4096,1,28,28] fp32
    const float* W     = (const float*)d_in[1];  // [10,784] fp32
    float* out         = (float*)d_out;          // [4096,10] fp32
    (void)in_sizes; (void)n_in; (void)out_size;

    snn_kernel<<<1024, 128>>>(image, W, out);
}

// round 12
// speedup vs baseline: 1.0093x; 1.0047x over previous
#include <cuda_runtime.h>
#include <math.h>

// TwoLayerNetwork: ConstantCurrentLIFEncoder -> LIFCell -> LILinearCell, T=32,
// then max over timesteps and log_softmax.
//
// Constants: DT*TAU_MEM_INV = 0.1 (decay 0.9), DT*TAU_SYN_INV = 0.2 (decay 0.8),
// V_TH = 1.0.
//
// EXACT per-row fast path (proof): v_enc follows v' = 0.9 v + 0.1 x from 0, so
// v_enc <= max_j x_j for all t. A spike needs v_enc > 1.0, so if ALL pixels of
// a row are <= 1.0 that row never spikes anywhere downstream: v_out stays 0 and
// the answer is log_softmax(zeros) = -log(10). Rows with a pixel > 1.0 run the
// full bit-exact simulator below, so correctness is input-independent.
//
// TERMINAL (R2..R11 evidence): bench time is 6.6-6.9us for EVERY configuration
// swept -- occupancy 11-35%, regs 40-128, loads 4B/16B/32B, grid 256-1024,
// 1-4 rows/warp, 1-2 kernels, L2 evict_last on/off -- with run-to-run noise
// +/-0.3us on identical source. Model: ~5us fixed one-shot launch/replay cost
// (a trivial kernel alone measured ~5us) + ~1.5-2us mandatory 12.8MB scan at
// the short-kernel memory ceiling. The scan is algorithmically irreducible
// (the exact spike predicate must read every pixel). This source is the
// twice-measured session best (6.624us).

#define NT 32
#define NPL 25   // neurons per lane (25*32 = 800 >= 784)

__global__ __launch_bounds__(128) void snn_kernel(
    const float* __restrict__ image,   // [4096, 784]
    const float* __restrict__ W,       // [10, 784]
    float* __restrict__ out)           // [4096, 10]
{
    const int lane = threadIdx.x & 31;
    const int b = blockIdx.x * 4 + (threadIdx.x >> 5);

    // Unconditional early write of the spike-free answer. Hot rows overwrite
    // below in program order (same thread), so the final value is always right.
    if (lane < 10)
        out[(size_t)b * 10 + lane] = -2.302585093f;  // log_softmax(zeros)

    const float* x = image + (size_t)b * 784;
    const float4* x4 = (const float4*)x;   // 196 vec4 per row

    // ---- vectorized row-max scan ----
    float m = 0.0f;
#pragma unroll
    for (int i = 0; i < 6; i++) {
        const float4 v = __ldg(&x4[lane + 32 * i]);
        m = fmaxf(m, fmaxf(fmaxf(v.x, v.y), fmaxf(v.z, v.w)));
    }
    if (lane < 4) {   // 196 = 6*32 + 4
        const float4 v = __ldg(&x4[lane + 192]);
        m = fmaxf(m, fmaxf(fmaxf(v.x, v.y), fmaxf(v.z, v.w)));
    }

    // Row provably spike-free -> constant already written, done.
    if (!__any_sync(0xffffffffu, m > 1.0f))
        return;

    // ---- Full general simulation (bit-exact verified R1 path) ----
    // Only rows that can actually spike reach here; reload in sim layout
    // (L2-hot). Register/spill cost is paid only on this path.
    float xs[NPL];   // 0.1 * x
    float ve[NPL];   // encoder membrane
    float v0[NPL];   // hidden membrane
    float i0[NPL];   // hidden synaptic current
#pragma unroll
    for (int i = 0; i < NPL; i++) {
        const int j = lane + 32 * i;
        xs[i] = (j < 784) ? 0.1f * __ldg(&x[j]) : 0.0f;
        ve[i] = 0.0f; v0[i] = 0.0f; i0[i] = 0.0f;
    }

    float v_out = 0.0f, i_out = 0.0f, vmax = -INFINITY;

#pragma unroll 1
    for (int t = 0; t < NT; t++) {
        unsigned tmask = 0u;
#pragma unroll
        for (int i = 0; i < NPL; i++) {
            // encoder LIF step
            float v = fmaf(ve[i], 0.9f, xs[i]);
            const bool pe = (v > 1.0f);
            const float zef = pe ? 1.0f : 0.0f;
            ve[i] = pe ? 0.0f : v;
            // hidden LIF step (reads old v0, i0)
            const float vd = fmaf(v0[i], 0.9f, 0.1f * i0[i]);
            const bool p0 = (vd > 1.0f);
            v0[i] = p0 ? 0.0f : vd;
            i0[i] = fmaf(i0[i], 0.8f, zef);
            if (p0) tmask |= (1u << i);
        }

        // s[k] = sum_j z0[j] * W[k, j]; zero on spike-free steps.
        float s = 0.0f;
        if (__any_sync(0xffffffffu, tmask != 0u)) {
            float acc[10];
#pragma unroll
            for (int k = 0; k < 10; k++) acc[k] = 0.0f;
            unsigned mm = tmask;
            while (mm) {
                const int i = __ffs(mm) - 1;
                mm &= (mm - 1u);
                const int j = lane + 32 * i;
#pragma unroll
                for (int k = 0; k < 10; k++)
                    acc[k] += __ldg(&W[k * 784 + j]);
            }
#pragma unroll
            for (int k = 0; k < 10; k++) {
#pragma unroll
                for (int off = 16; off; off >>= 1)
                    acc[k] += __shfl_xor_sync(0xffffffffu, acc[k], off);
            }
            s = acc[0];
#pragma unroll
            for (int k = 1; k < 10; k++) s = (lane == k) ? acc[k] : s;
        }

        const float i_jump = i_out + s;
        v_out = fmaf(v_out, 0.9f, 0.1f * i_jump);
        i_out = 0.8f * i_jump;
        vmax = fmaxf(vmax, v_out);
    }

    // log_softmax over the 10 classes held by lanes 0..9
    const float v = (lane < 10) ? vmax : -INFINITY;
    float mred = v;
#pragma unroll
    for (int off = 16; off; off >>= 1)
        mred = fmaxf(mred, __shfl_xor_sync(0xffffffffu, mred, off));
    float e = (lane < 10) ? expf(v - mred) : 0.0f;
    float se = e;
#pragma unroll
    for (int off = 16; off; off >>= 1)
        se += __shfl_xor_sync(0xffffffffu, se, off);

    if (lane < 10)
        out[(size_t)b * 10 + lane] = v - mred - logf(se);
}

extern "C" void kernel_launch(void* const* d_in, const int* in_sizes, int n_in,
                              void* d_out, int out_size) {
    const float* image = (const float*)d_in[0];  // [4096,1,28,28] fp32
    const float* W     = (const float*)d_in[1];  // [10,784] fp32
    float* out         = (float*)d_out;          // [4096,10] fp32
    (void)in_sizes; (void)n_in; (void)out_size;

    snn_kernel<<<1024, 128>>>(image, W, out);
}

// round 13
// speedup vs baseline: 1.0385x; 1.0288x over previous
#include <cuda_runtime.h>
#include <math.h>

// TwoLayerNetwork: ConstantCurrentLIFEncoder -> LIFCell -> LILinearCell, T=32,
// then max over timesteps and log_softmax.
//
// Constants: DT*TAU_MEM_INV = 0.1 (decay 0.9), DT*TAU_SYN_INV = 0.2 (decay 0.8),
// V_TH = 1.0.
//
// EXACT per-row fast path (proof): v_enc follows v' = 0.9 v + 0.1 x from 0, so
// v_enc <= max_j x_j for all t. A spike needs v_enc > 1.0, so if ALL pixels of
// a row are <= 1.0 that row never spikes anywhere downstream: v_out stays 0 and
// the answer is log_softmax(zeros) = -log(10). Rows with a pixel > 1.0 run the
// full bit-exact simulator below, so correctness is input-independent.
//
// TERMINAL (R2..R12 evidence): identical source benched 6.624/6.912/6.848us;
// every swept knob (occ 11-35%, regs 40-128, loads 4B/16B/32B, grid 256-1024,
// 1-4 rows/warp, 1-2 kernels, L2 evict_last) is timing-neutral. Model:
// ~5us fixed one-shot launch/replay cost (trivial kernel measured ~5us alone)
// + ~1.6us mandatory 12.8MB scan at the short-kernel memory ceiling
// (~2TB/s, invariant under all software knobs). Traffic is provably minimal:
// the spike predicate must inspect every pixel and every 32B sector of the
// contiguous image contains pixels. 48.1us (optimal full sim) -> 6.6us.

#define NT 32
#define NPL 25   // neurons per lane (25*32 = 800 >= 784)

__global__ __launch_bounds__(128) void snn_kernel(
    const float* __restrict__ image,   // [4096, 784]
    const float* __restrict__ W,       // [10, 784]
    float* __restrict__ out)           // [4096, 10]
{
    const int lane = threadIdx.x & 31;
    const int b = blockIdx.x * 4 + (threadIdx.x >> 5);

    // Unconditional early write of the spike-free answer. Hot rows overwrite
    // below in program order (same thread), so the final value is always right.
    if (lane < 10)
        out[(size_t)b * 10 + lane] = -2.302585093f;  // log_softmax(zeros)

    const float* x = image + (size_t)b * 784;
    const float4* x4 = (const float4*)x;   // 196 vec4 per row

    // ---- vectorized row-max scan ----
    float m = 0.0f;
#pragma unroll
    for (int i = 0; i < 6; i++) {
        const float4 v = __ldg(&x4[lane + 32 * i]);
        m = fmaxf(m, fmaxf(fmaxf(v.x, v.y), fmaxf(v.z, v.w)));
    }
    if (lane < 4) {   // 196 = 6*32 + 4
        const float4 v = __ldg(&x4[lane + 192]);
        m = fmaxf(m, fmaxf(fmaxf(v.x, v.y), fmaxf(v.z, v.w)));
    }

    // Row provably spike-free -> constant already written, done.
    if (!__any_sync(0xffffffffu, m > 1.0f))
        return;

    // ---- Full general simulation (bit-exact verified R1 path) ----
    // Only rows that can actually spike reach here; reload in sim layout
    // (L2-hot). Register/spill cost is paid only on this path.
    float xs[NPL];   // 0.1 * x
    float ve[NPL];   // encoder membrane
    float v0[NPL];   // hidden membrane
    float i0[NPL];   // hidden synaptic current
#pragma unroll
    for (int i = 0; i < NPL; i++) {
        const int j = lane + 32 * i;
        xs[i] = (j < 784) ? 0.1f * __ldg(&x[j]) : 0.0f;
        ve[i] = 0.0f; v0[i] = 0.0f; i0[i] = 0.0f;
    }

    float v_out = 0.0f, i_out = 0.0f, vmax = -INFINITY;

#pragma unroll 1
    for (int t = 0; t < NT; t++) {
        unsigned tmask = 0u;
#pragma unroll
        for (int i = 0; i < NPL; i++) {
            // encoder LIF step
            float v = fmaf(ve[i], 0.9f, xs[i]);
            const bool pe = (v > 1.0f);
            const float zef = pe ? 1.0f : 0.0f;
            ve[i] = pe ? 0.0f : v;
            // hidden LIF step (reads old v0, i0)
            const float vd = fmaf(v0[i], 0.9f, 0.1f * i0[i]);
            const bool p0 = (vd > 1.0f);
            v0[i] = p0 ? 0.0f : vd;
            i0[i] = fmaf(i0[i], 0.8f, zef);
            if (p0) tmask |= (1u << i);
        }

        // s[k] = sum_j z0[j] * W[k, j]; zero on spike-free steps.
        float s = 0.0f;
        if (__any_sync(0xffffffffu, tmask != 0u)) {
            float acc[10];
#pragma unroll
            for (int k = 0; k < 10; k++) acc[k] = 0.0f;
            unsigned mm = tmask;
            while (mm) {
                const int i = __ffs(mm) - 1;
                mm &= (mm - 1u);
                const int j = lane + 32 * i;
#pragma unroll
                for (int k = 0; k < 10; k++)
                    acc[k] += __ldg(&W[k * 784 + j]);
            }
#pragma unroll
            for (int k = 0; k < 10; k++) {
#pragma unroll
                for (int off = 16; off; off >>= 1)
                    acc[k] += __shfl_xor_sync(0xffffffffu, acc[k], off);
            }
            s = acc[0];
#pragma unroll
            for (int k = 1; k < 10; k++) s = (lane == k) ? acc[k] : s;
        }

        const float i_jump = i_out + s;
        v_out = fmaf(v_out, 0.9f, 0.1f * i_jump);
        i_out = 0.8f * i_jump;
        vmax = fmaxf(vmax, v_out);
    }

    // log_softmax over the 10 classes held by lanes 0..9
    const float v = (lane < 10) ? vmax : -INFINITY;
    float mred = v;
#pragma unroll
    for (int off = 16; off; off >>= 1)
        mred = fmaxf(mred, __shfl_xor_sync(0xffffffffu, mred, off));
    float e = (lane < 10) ? expf(v - mred) : 0.0f;
    float se = e;
#pragma unroll
    for (int off = 16; off; off >>= 1)
        se += __shfl_xor_sync(0xffffffffu, se, off);

    if (lane < 10)
        out[(size_t)b * 10 + lane] = v - mred - logf(se);
}

extern "C" void kernel_launch(void* const* d_in, const int* in_sizes, int n_in,
                              void* d_out, int out_size) {
    const float* image = (const float*)d_in[0];  // [4096,1,28,28] fp32
    const float* W     = (const float*)d_in[1];  // [10,784] fp32
    float* out         = (float*)d_out;          // [4096,10] fp32
    (void)in_sizes; (void)n_in; (void)out_size;

    snn_kernel<<<1024, 128>>>(image, W, out);
}